// round 12
// baseline (speedup 1.0000x reference)
#include <cuda_runtime.h>
#include <math.h>

// Problem dims
#define N_   256
#define T_   128
#define D_   512
#define H_   1024
#define OUT_ 128

// LSTM-step GEMM tiling
#define BM 64      // batch rows per CTA
#define BH 32      // h-columns per CTA (x4 gates = 128 gate-cols)
#define BK 16      // k-depth per smem tile (double-buffered)

typedef unsigned long long u64;

// Persistent scratch (device-global: allocations are forbidden). Re-zeroed by
// init_kernel on every replay so the captured graph stays deterministic.
__device__ float g_h[2][N_ * H_];   // ping-pong hidden state
__device__ float g_c[N_ * H_];      // cell state (in place)

// ---------------------------------------------------------------------------
__global__ void init_kernel() {
    int idx = blockIdx.x * blockDim.x + threadIdx.x;
    if (idx < N_ * H_) {
        g_h[0][idx] = 0.0f;
        g_c[idx]    = 0.0f;
    }
}

__device__ __forceinline__ float fsigmoid(float z) {
    return 1.0f / (1.0f + __expf(-z));
}
__device__ __forceinline__ float ftanh(float z) {
    // 1 - 2/(e^{2z}+1); saturates correctly for |z| large
    return 1.0f - 2.0f / (__expf(2.0f * z) + 1.0f);
}

// Packed f32x2 helpers (sm_100+): two independent IEEE fp32 ops per instr,
// bit-identical to the scalar sequence.
__device__ __forceinline__ u64 pack_f32x2(float lo, float hi) {
    u64 r;
    asm("mov.b64 %0, {%1, %2};" : "=l"(r) : "f"(lo), "f"(hi));
    return r;
}
__device__ __forceinline__ void unpack_f32x2(float& lo, float& hi, u64 v) {
    asm("mov.b64 {%0, %1}, %2;" : "=f"(lo), "=f"(hi) : "l"(v));
}
__device__ __forceinline__ void fma_f32x2(u64& d, u64 a, u64 b) {
    asm("fma.rn.f32x2 %0, %1, %2, %0;" : "+l"(d) : "l"(a), "l"(b));
}

// ---------------------------------------------------------------------------
// Fused LSTM step.
//   gates[m, g, h] = x[m,t,:]·W_ih[g*H+h,:] + h_prev[m,:]·W_hh[g*H+h,:]
//                  + b_ih[gH+h] + b_hh[gH+h]
// CTA tile: 64 rows x 32 h x 4 gates (128 gate-cols). Grid (32, 4) = 128 CTAs
// (single wave on 148 SMs). 256 threads; thread (tx,ty) owns rows 4ty..4ty+3
// and gate-interleaved columns c' = 4tx..+3 and 64+4tx..+3, c' = 4*h_local+gate.
// Each thread holds ALL FOUR gates for (4 rows x 2 h-cols): the cell update is
// fully thread-local, single-owner.
//
// Inner product uses fma.rn.f32x2: accumulators are 16 packed u64 (pairs along
// the gate-column axis), B fragments are read as ulonglong2 (same LDS.128,
// even/odd reg pairs), A broadcast packed {a,a} once per row. Per-SMSP FFMA
// issue per k-tile drops 128 -> 64 cyc; kernel becomes LDS/issue bound
// (~90-100 cyc). Two-stage double buffer, one __syncthreads per K-tile.
// Shared tiles force-aligned 16B (LDS.128 on a 4B base would trap).
// ---------------------------------------------------------------------------
__global__ __launch_bounds__(256)
void lstm_step_kernel(const float* __restrict__ x,     // [N, T, D]
                      const float* __restrict__ W_ih,  // [4H, D]
                      const float* __restrict__ W_hh,  // [4H, H]
                      const float* __restrict__ b_ih,  // [4H]
                      const float* __restrict__ b_hh,  // [4H]
                      int t)
{
    __shared__ __align__(16) float As[2][BK][BM + 4];   // row stride 68 = 17x16B
    __shared__ __align__(16) float Bs[2][BK][128 + 4];  // row stride 132 = 33x16B

    const int tid = threadIdx.x;
    const int tx  = tid & 15;
    const int ty  = tid >> 4;
    const int h0  = blockIdx.x * BH;
    const int m0  = blockIdx.y * BM;

    const float* __restrict__ h_in  = g_h[t & 1];
    float* __restrict__       h_out = g_h[(t + 1) & 1];

    // acc2[i][q] = packed pair of gate-columns (2q, 2q+1) for row i.
    u64 acc2[4][4];
#pragma unroll
    for (int i = 0; i < 4; i++)
#pragma unroll
        for (int q = 0; q < 4; q++) acc2[i][q] = 0ULL;   // {0.0f, 0.0f}

    // Per-thread load assignments (identical pattern both phases):
    // A tile (64 rows x 16 k): 256 float4 -> 1 per thread.
    const int a_row = tid >> 2;              // 0..63
    const int a_kp  = (tid & 3) << 2;        // 0,4,8,12
    // B tile (128 gate-cols x 16 k): 512 float4 -> 2 per thread.
    int b_c[2], b_R[2];
    const int b_kp = (tid & 3) << 2;
#pragma unroll
    for (int r = 0; r < 2; r++) {
        int idx = tid + 256 * r;
        int c   = idx >> 2;                  // interleaved col: 4*h_local+gate
        int h_local = c >> 2;
        int gate    = c & 3;
        b_c[r] = c;
        b_R[r] = gate * H_ + h0 + h_local;   // weight row
    }

#pragma unroll 1
    for (int phase = 0; phase < 2; phase++) {
        const float* __restrict__ A = (phase == 0) ? (x + (long)t * D_) : h_in;
        const long  a_stride        = (phase == 0) ? (long)T_ * D_ : (long)H_;
        const float* __restrict__ W = (phase == 0) ? W_ih : W_hh;
        const int   Kdim            = (phase == 0) ? D_ : H_;
        const int   ktiles          = Kdim / BK;

        const float* a_src  = A + (long)(m0 + a_row) * a_stride + a_kp;
        const float* b_src0 = W + (long)b_R[0] * Kdim + b_kp;
        const float* b_src1 = W + (long)b_R[1] * Kdim + b_kp;

        // Prologue: tile 0 -> buffer 0
        float4 pa  = *reinterpret_cast<const float4*>(a_src);
        float4 pb0 = *reinterpret_cast<const float4*>(b_src0);
        float4 pb1 = *reinterpret_cast<const float4*>(b_src1);
        int buf = 0;
        As[buf][a_kp + 0][a_row] = pa.x;  As[buf][a_kp + 1][a_row] = pa.y;
        As[buf][a_kp + 2][a_row] = pa.z;  As[buf][a_kp + 3][a_row] = pa.w;
        Bs[buf][b_kp + 0][b_c[0]] = pb0.x; Bs[buf][b_kp + 1][b_c[0]] = pb0.y;
        Bs[buf][b_kp + 2][b_c[0]] = pb0.z; Bs[buf][b_kp + 3][b_c[0]] = pb0.w;
        Bs[buf][b_kp + 0][b_c[1]] = pb1.x; Bs[buf][b_kp + 1][b_c[1]] = pb1.y;
        Bs[buf][b_kp + 2][b_c[1]] = pb1.z; Bs[buf][b_kp + 3][b_c[1]] = pb1.w;
        __syncthreads();

#pragma unroll 1
        for (int kt = 0; kt < ktiles; kt++) {
            const bool has_next = (kt + 1) < ktiles;
            if (has_next) {
                int ko = (kt + 1) * BK;
                pa  = *reinterpret_cast<const float4*>(a_src  + ko);
                pb0 = *reinterpret_cast<const float4*>(b_src0 + ko);
                pb1 = *reinterpret_cast<const float4*>(b_src1 + ko);
            }

#pragma unroll
            for (int kk = 0; kk < BK; kk++) {
                float4 a4 = *reinterpret_cast<const float4*>(&As[buf][kk][ty << 2]);
                ulonglong2 bA = *reinterpret_cast<const ulonglong2*>(&Bs[buf][kk][tx << 2]);
                ulonglong2 bB = *reinterpret_cast<const ulonglong2*>(&Bs[buf][kk][64 + (tx << 2)]);
                u64 bp[4] = {bA.x, bA.y, bB.x, bB.y};
                u64 ap[4];
                ap[0] = pack_f32x2(a4.x, a4.x);
                ap[1] = pack_f32x2(a4.y, a4.y);
                ap[2] = pack_f32x2(a4.z, a4.z);
                ap[3] = pack_f32x2(a4.w, a4.w);
#pragma unroll
                for (int i = 0; i < 4; i++)
#pragma unroll
                    for (int q = 0; q < 4; q++)
                        fma_f32x2(acc2[i][q], ap[i], bp[q]);
            }

            if (has_next) {
                int nb = buf ^ 1;
                As[nb][a_kp + 0][a_row] = pa.x;  As[nb][a_kp + 1][a_row] = pa.y;
                As[nb][a_kp + 2][a_row] = pa.z;  As[nb][a_kp + 3][a_row] = pa.w;
                Bs[nb][b_kp + 0][b_c[0]] = pb0.x; Bs[nb][b_kp + 1][b_c[0]] = pb0.y;
                Bs[nb][b_kp + 2][b_c[0]] = pb0.z; Bs[nb][b_kp + 3][b_c[0]] = pb0.w;
                Bs[nb][b_kp + 0][b_c[1]] = pb1.x; Bs[nb][b_kp + 1][b_c[1]] = pb1.y;
                Bs[nb][b_kp + 2][b_c[1]] = pb1.z; Bs[nb][b_kp + 3][b_c[1]] = pb1.w;
                buf = nb;
            }
            __syncthreads();
        }
    }

    // Unpack pairs: acc2[i][q] holds gate-columns (2q, 2q+1) = acc[i][2q..2q+1].
    // Mapping unchanged from scalar version: acc[i][4p+g], h = h0+tx+16p.
    float acc[4][8];
#pragma unroll
    for (int i = 0; i < 4; i++)
#pragma unroll
        for (int q = 0; q < 4; q++)
            unpack_f32x2(acc[i][2 * q], acc[i][2 * q + 1], acc2[i][q]);

#pragma unroll
    for (int p = 0; p < 2; p++) {
        const int h  = h0 + tx + 16 * p;
        const float bi = __ldg(b_ih + h)          + __ldg(b_hh + h);
        const float bf = __ldg(b_ih + H_ + h)     + __ldg(b_hh + H_ + h);
        const float bg = __ldg(b_ih + 2 * H_ + h) + __ldg(b_hh + 2 * H_ + h);
        const float bo = __ldg(b_ih + 3 * H_ + h) + __ldg(b_hh + 3 * H_ + h);
#pragma unroll
        for (int i = 0; i < 4; i++) {
            const int m = m0 + (ty << 2) + i;
            float ig = fsigmoid(acc[i][4 * p + 0] + bi);
            float fg = fsigmoid(acc[i][4 * p + 1] + bf);
            float gg = ftanh   (acc[i][4 * p + 2] + bg);
            float og = fsigmoid(acc[i][4 * p + 3] + bo);

            const int idx = m * H_ + h;
            float c = fg * g_c[idx] + ig * gg;
            g_c[idx]   = c;
            h_out[idx] = og * ftanh(c);
        }
    }
}

// ---------------------------------------------------------------------------
// Dense layer: C[M, Nc] = act(A[M, K] @ W[Nc, K]^T + b). 64x64 tiles, BK=32,
// 256 threads, 4x4 per-thread. a_is_h selects the persistent final h state.
// (<2% of total runtime; scalar-LDS single-buffer tiling is fine here.)
// ---------------------------------------------------------------------------
__global__ __launch_bounds__(256)
void dense_kernel(const float* __restrict__ A_in,
                  int a_is_h,
                  const float* __restrict__ W,   // [Nc, K]
                  const float* __restrict__ b,   // [Nc]
                  float* __restrict__ C,         // [M, Nc]
                  int Nc, int K, int do_relu)
{
    __shared__ __align__(16) float As[32][65];
    __shared__ __align__(16) float Bs[32][65];

    const float* __restrict__ A = a_is_h ? g_h[0] : A_in;

    const int tid = threadIdx.x;
    const int tx  = tid & 15;
    const int ty  = tid >> 4;
    const int n0  = blockIdx.x * 64;
    const int m0  = blockIdx.y * 64;

    float acc[4][4];
#pragma unroll
    for (int i = 0; i < 4; i++)
#pragma unroll
        for (int j = 0; j < 4; j++) acc[i][j] = 0.0f;

    for (int k0 = 0; k0 < K; k0 += 32) {
#pragma unroll
        for (int r = 0; r < 2; r++) {
            int idx = tid + 256 * r;
            int row = idx >> 3;
            int kp  = (idx & 7) << 2;
            float4 va = *reinterpret_cast<const float4*>(
                A + (long)(m0 + row) * K + k0 + kp);
            As[kp + 0][row] = va.x; As[kp + 1][row] = va.y;
            As[kp + 2][row] = va.z; As[kp + 3][row] = va.w;
            float4 vb = *reinterpret_cast<const float4*>(
                W + (long)(n0 + row) * K + k0 + kp);
            Bs[kp + 0][row] = vb.x; Bs[kp + 1][row] = vb.y;
            Bs[kp + 2][row] = vb.z; Bs[kp + 3][row] = vb.w;
        }
        __syncthreads();

#pragma unroll 8
        for (int kk = 0; kk < 32; kk++) {
            float a[4], bb[4];
#pragma unroll
            for (int i = 0; i < 4; i++) a[i]  = As[kk][ty + 16 * i];
#pragma unroll
            for (int j = 0; j < 4; j++) bb[j] = Bs[kk][tx + 16 * j];
#pragma unroll
            for (int i = 0; i < 4; i++)
#pragma unroll
                for (int j = 0; j < 4; j++) acc[i][j] += a[i] * bb[j];
        }
        __syncthreads();
    }

#pragma unroll
    for (int i = 0; i < 4; i++) {
        int m = m0 + ty + 16 * i;
#pragma unroll
        for (int j = 0; j < 4; j++) {
            int n   = n0 + tx + 16 * j;
            float v = acc[i][j] + __ldg(b + n);
            if (do_relu) v = fmaxf(v, 0.0f);
            C[(long)m * Nc + n] = v;
        }
    }
}

// ---------------------------------------------------------------------------
// Launcher: init -> 128 fused LSTM steps -> ReLU head -> output head.
// d_out layout: [0 : 256*128) = output, then [.. : +256*1024) = pre_output.
// ---------------------------------------------------------------------------
extern "C" void kernel_launch(void* const* d_in, const int* in_sizes, int n_in,
                              void* d_out, int out_size)
{
    const float* x    = (const float*)d_in[0];
    const float* W_ih = (const float*)d_in[1];
    const float* W_hh = (const float*)d_in[2];
    const float* b_ih = (const float*)d_in[3];
    const float* b_hh = (const float*)d_in[4];
    const float* W1   = (const float*)d_in[5];
    const float* b1   = (const float*)d_in[6];
    const float* W2   = (const float*)d_in[7];
    const float* b2   = (const float*)d_in[8];
    float* out = (float*)d_out;

    float* out_final = out;                  // [256, 128]
    float* out_pre   = out + N_ * OUT_;      // [256, 1024]

    init_kernel<<<(N_ * H_ + 255) / 256, 256>>>();

    for (int t = 0; t < T_; t++) {
        lstm_step_kernel<<<dim3(H_ / BH, N_ / BM), 256>>>(
            x, W_ih, W_hh, b_ih, b_hh, t);
    }

    // pre_output = relu(last_h @ W1^T + b1); last_h is g_h[0] (T even).
    dense_kernel<<<dim3(H_ / 64, N_ / 64), 256>>>(
        nullptr, /*a_is_h=*/1, W1, b1, out_pre, H_, H_, /*relu=*/1);

    // output = pre_output @ W2^T + b2
    dense_kernel<<<dim3(OUT_ / 64, N_ / 64), 256>>>(
        out_pre, /*a_is_h=*/0, W2, b2, out_final, OUT_, H_, /*relu=*/0);
}